// round 5
// baseline (speedup 1.0000x reference)
#include <cuda_runtime.h>

#define NN   100000
#define DD   128
#define EE   600000
#define SS   2
#define HIDN 80
#define NOUT 2

#define SUM_GRID  296
#define SUM_BLK   256
#define SUM_U     8

// Scratch (allocation-free: __device__ globals, zero-initialized at load)
__device__ unsigned char g_mask[SS * NN];   // dst indicator; SELF-CLEARING in k_sum
__device__ float g_sum[SS * DD];            // masked column sums (zeroed by k_mask)
__device__ unsigned int g_ticket;           // last-block ticket (reset by last block)

// ---------------------------------------------------------------------------
// K1: zero g_sum (block 0) + scatter dst-mask. edges (S,E,2) int32.
// int4 = 2 edges; .y and .w are the dst fields.
// ---------------------------------------------------------------------------
__global__ void k_mask(const int4* __restrict__ edges4) {
    const int idx = blockIdx.x * blockDim.x + threadIdx.x;
    if (blockIdx.x == 0 && threadIdx.x < SS * DD) g_sum[threadIdx.x] = 0.0f;

    const int total4 = SS * EE / 2;      // 600000 int4 (2 edges each)
    const int half   = EE / 2;           // int4 index where edge set 1 begins
    if (idx < total4) {
        int4 v = edges4[idx];
        int s_off = (idx >= half) ? NN : 0;
        g_mask[s_off + v.y] = 1;
        g_mask[s_off + v.w] = 1;
    }
}

// ---------------------------------------------------------------------------
// K2 (fused): masked column sums -> last block does GEMV + MLP.
//   - float4 loads, 8 rows/block-step (8 warps), unroll x8
//   - mask self-clears (all lanes store 0 after the broadcast read)
//   - block partials reduced in smem, then atomics into g_sum
//   - threadfence + ticket; last block: x = (sum0@W0 + sum1@W1)/N, MLP -> out
// ---------------------------------------------------------------------------
__device__ __forceinline__ float lrelu(float x) {
    return x > 0.0f ? x : 0.01f * x;
}

__device__ __forceinline__ float warp_reduce(float v) {
#pragma unroll
    for (int off = 16; off > 0; off >>= 1)
        v += __shfl_down_sync(0xFFFFFFFFu, v, off);
    return v;
}

__global__ void __launch_bounds__(SUM_BLK)
k_sum_fused(const float4* __restrict__ nodes4,
            const float* __restrict__ W,
            const float* __restrict__ pt,
            const float* __restrict__ fc1w, const float* __restrict__ fc1b,
            const float* __restrict__ fc2w, const float* __restrict__ fc2b,
            const float* __restrict__ fc3w, const float* __restrict__ fc3b,
            float* __restrict__ out) {
    const int tid = threadIdx.x;
    const int q = tid & 31;    // float4 column group (cols 4q..4q+3)
    const int r = tid >> 5;    // 0..7 row-subwarp
    const int G = SUM_GRID;

    float4 a0 = make_float4(0.f, 0.f, 0.f, 0.f);
    float4 a1 = make_float4(0.f, 0.f, 0.f, 0.f);

    for (int n0 = blockIdx.x * 8 + r; n0 < NN; n0 += 8 * G * SUM_U) {
#pragma unroll
        for (int u = 0; u < SUM_U; u++) {
            int nn = n0 + u * 8 * G;
            if (nn < NN) {
                float4 v = nodes4[(size_t)nn * 32 + q];
                float m0 = (float)g_mask[nn];
                float m1 = (float)g_mask[NN + nn];
                // self-clear for next replay (all lanes store same value)
                g_mask[nn] = 0;
                g_mask[NN + nn] = 0;
                a0.x += v.x * m0; a0.y += v.y * m0; a0.z += v.z * m0; a0.w += v.w * m0;
                a1.x += v.x * m1; a1.y += v.y * m1; a1.z += v.z * m1; a1.w += v.w * m1;
            }
        }
    }

    __shared__ float4 sp0[8][32], sp1[8][32];
    sp0[r][q] = a0; sp1[r][q] = a1;
    __syncthreads();
    if (r == 0) {
#pragma unroll
        for (int i = 1; i < 8; i++) {
            float4 b0 = sp0[i][q], b1 = sp1[i][q];
            a0.x += b0.x; a0.y += b0.y; a0.z += b0.z; a0.w += b0.w;
            a1.x += b1.x; a1.y += b1.y; a1.z += b1.z; a1.w += b1.w;
        }
        atomicAdd(&g_sum[4 * q + 0], a0.x);
        atomicAdd(&g_sum[4 * q + 1], a0.y);
        atomicAdd(&g_sum[4 * q + 2], a0.z);
        atomicAdd(&g_sum[4 * q + 3], a0.w);
        atomicAdd(&g_sum[DD + 4 * q + 0], a1.x);
        atomicAdd(&g_sum[DD + 4 * q + 1], a1.y);
        atomicAdd(&g_sum[DD + 4 * q + 2], a1.z);
        atomicAdd(&g_sum[DD + 4 * q + 3], a1.w);
    }
    __syncthreads();

    // ---- last-block election ----
    __shared__ unsigned int s_last;
    if (tid == 0) {
        __threadfence();
        unsigned int old = atomicAdd(&g_ticket, 1u);
        s_last = (old == (unsigned)(G - 1)) ? 1u : 0u;
    }
    __syncthreads();
    if (!s_last) return;

    // ---- epilogue (one block, 256 threads): GEMV + MLP ----
    __shared__ float sh0[DD], sh1[DD], xv[DD + 1], h1[HIDN], h2[HIDN];
    __shared__ float xpart[SUM_BLK];

    if (tid < DD) { sh0[tid] = g_sum[tid]; sh1[tid] = g_sum[DD + tid]; }
    __syncthreads();

    // GEMV split: col = tid&127, half = tid>>7 covers k in [64*half, 64*half+64)
    {
        const int col = tid & (DD - 1);
        const int h = tid >> 7;
        float acc = 0.0f;
#pragma unroll 8
        for (int k = h * 64; k < h * 64 + 64; k++) {
            acc += sh0[k] * W[k * DD + col];
            acc += sh1[k] * W[DD * DD + k * DD + col];
        }
        xpart[tid] = acc;
    }
    __syncthreads();
    if (tid < DD) xv[tid] = (xpart[tid] + xpart[tid + DD]) * (1.0f / (float)NN);
    if (tid == 0) xv[DD] = pt[0];
    __syncthreads();

    const int warp = tid >> 5;   // 0..7
    const int lane = tid & 31;

    // fc1: 80 x 129
    for (int row = warp; row < HIDN; row += 8) {
        float a = 0.0f;
#pragma unroll
        for (int j0 = 0; j0 < DD + 1; j0 += 32) {
            int j = j0 + lane;
            if (j < DD + 1) a += xv[j] * fc1w[row * (DD + 1) + j];
        }
        a = warp_reduce(a);
        if (lane == 0) h1[row] = lrelu(a + fc1b[row]);
    }
    __syncthreads();

    // fc2: 80 x 80
    for (int row = warp; row < HIDN; row += 8) {
        float a = 0.0f;
#pragma unroll
        for (int j0 = 0; j0 < HIDN; j0 += 32) {
            int j = j0 + lane;
            if (j < HIDN) a += h1[j] * fc2w[row * HIDN + j];
        }
        a = warp_reduce(a);
        if (lane == 0) h2[row] = lrelu(a + fc2b[row]);
    }
    __syncthreads();

    // fc3: 2 x 80
    if (warp < NOUT) {
        float a = 0.0f;
#pragma unroll
        for (int j0 = 0; j0 < HIDN; j0 += 32) {
            int j = j0 + lane;
            if (j < HIDN) a += h2[j] * fc3w[warp * HIDN + j];
        }
        a = warp_reduce(a);
        if (lane == 0) out[warp] = a + fc3b[warp];
    }

    // reset ticket for next replay (only this block is alive)
    if (tid == 0) g_ticket = 0u;
}

// ---------------------------------------------------------------------------
// Input order: nodes, edges, problem_type, W, att_w, att_b,
//              fc1_w, fc1_b, fc2_w, fc2_b, fc3_w, fc3_b
// att_w/att_b provably unused (segment softmax weights sum to 1 per dst;
// scatter-sum then makes the attention collapse to a masked column sum).
// ---------------------------------------------------------------------------
extern "C" void kernel_launch(void* const* d_in, const int* in_sizes, int n_in,
                              void* d_out, int out_size) {
    const float4* nodes4 = (const float4*)d_in[0];
    const int4*   edges4 = (const int4*)d_in[1];
    const float*  pt     = (const float*)d_in[2];
    const float*  W      = (const float*)d_in[3];
    const float*  fc1w   = (const float*)d_in[6];
    const float*  fc1b   = (const float*)d_in[7];
    const float*  fc2w   = (const float*)d_in[8];
    const float*  fc2b   = (const float*)d_in[9];
    const float*  fc3w   = (const float*)d_in[10];
    const float*  fc3b   = (const float*)d_in[11];
    float* out = (float*)d_out;

    const int mask_blocks = (SS * EE / 2 + 255) / 256;  // 2344
    k_mask<<<mask_blocks, 256>>>(edges4);
    k_sum_fused<<<SUM_GRID, SUM_BLK>>>(nodes4, W, pt,
                                       fc1w, fc1b, fc2w, fc2b, fc3w, fc3b, out);
}

// round 6
// speedup vs baseline: 2.4590x; 2.4590x over previous
#include <cuda_runtime.h>

#define NN   100000
#define DD   128
#define EE   600000
#define SS   2
#define HIDN 80
#define NOUT 2

#define SUM_GRID  296
#define SUM_BLK   256
#define SUM_U     8

// Scratch (allocation-free: __device__ globals, zero-initialized at load)
__device__ unsigned int g_mask[SS * NN];   // generation-tagged dst indicator
__device__ float g_sum[SS * DD];           // masked column sums (zeroed by k_mask)
__device__ unsigned int g_ticket;          // last-block ticket (reset by epilogue)
__device__ unsigned int g_gen;             // committed generation (epilogue bumps)

// ---------------------------------------------------------------------------
// K1: zero g_sum (block 0) + scatter dst-mask with NEW generation tag.
// edges (S,E,2) int32; int4 = 2 edges; .y and .w are dst fields.
// New gen = g_gen + 1 (g_gen is committed by the previous replay's epilogue,
// so it is stable throughout this kernel). No mask clearing ever needed:
// entries from older generations simply don't match.
// ---------------------------------------------------------------------------
__global__ void k_mask(const int4* __restrict__ edges4) {
    const int idx = blockIdx.x * blockDim.x + threadIdx.x;
    if (blockIdx.x == 0 && threadIdx.x < SS * DD) g_sum[threadIdx.x] = 0.0f;

    const unsigned int gen = g_gen + 1u;
    const int total4 = SS * EE / 2;      // 600000 int4 (2 edges each)
    const int half   = EE / 2;           // int4 index where edge set 1 begins
    if (idx < total4) {
        int4 v = edges4[idx];
        int s_off = (idx >= half) ? NN : 0;
        g_mask[s_off + v.y] = gen;
        g_mask[s_off + v.w] = gen;
    }
}

// ---------------------------------------------------------------------------
// K2 (fused): masked column sums -> last block does GEMV + MLP.
//   - pure read stream: float4 node loads + L2-resident mask reads, NO stores
//   - block partials reduced in smem, then atomics into g_sum
//   - threadfence + ticket; last block: x = (sum0@W0 + sum1@W1)/N, MLP -> out
//   - epilogue commits g_gen and resets ticket
// ---------------------------------------------------------------------------
__device__ __forceinline__ float lrelu(float x) {
    return x > 0.0f ? x : 0.01f * x;
}

__device__ __forceinline__ float warp_reduce(float v) {
#pragma unroll
    for (int off = 16; off > 0; off >>= 1)
        v += __shfl_down_sync(0xFFFFFFFFu, v, off);
    return v;
}

__global__ void __launch_bounds__(SUM_BLK)
k_sum_fused(const float4* __restrict__ nodes4,
            const float* __restrict__ W,
            const float* __restrict__ pt,
            const float* __restrict__ fc1w, const float* __restrict__ fc1b,
            const float* __restrict__ fc2w, const float* __restrict__ fc2b,
            const float* __restrict__ fc3w, const float* __restrict__ fc3b,
            float* __restrict__ out) {
    const int tid = threadIdx.x;
    const int q = tid & 31;    // float4 column group (cols 4q..4q+3)
    const int r = tid >> 5;    // 0..7 row-subwarp
    const int G = SUM_GRID;
    const unsigned int gen = g_gen + 1u;   // generation k_mask just wrote

    float4 a0 = make_float4(0.f, 0.f, 0.f, 0.f);
    float4 a1 = make_float4(0.f, 0.f, 0.f, 0.f);

    for (int n0 = blockIdx.x * 8 + r; n0 < NN; n0 += 8 * G * SUM_U) {
#pragma unroll
        for (int u = 0; u < SUM_U; u++) {
            int nn = n0 + u * 8 * G;
            if (nn < NN) {
                float4 v = nodes4[(size_t)nn * 32 + q];
                float m0 = (g_mask[nn]      == gen) ? 1.0f : 0.0f;
                float m1 = (g_mask[NN + nn] == gen) ? 1.0f : 0.0f;
                a0.x += v.x * m0; a0.y += v.y * m0; a0.z += v.z * m0; a0.w += v.w * m0;
                a1.x += v.x * m1; a1.y += v.y * m1; a1.z += v.z * m1; a1.w += v.w * m1;
            }
        }
    }

    __shared__ float4 sp0[8][32], sp1[8][32];
    sp0[r][q] = a0; sp1[r][q] = a1;
    __syncthreads();
    if (r == 0) {
#pragma unroll
        for (int i = 1; i < 8; i++) {
            float4 b0 = sp0[i][q], b1 = sp1[i][q];
            a0.x += b0.x; a0.y += b0.y; a0.z += b0.z; a0.w += b0.w;
            a1.x += b1.x; a1.y += b1.y; a1.z += b1.z; a1.w += b1.w;
        }
        atomicAdd(&g_sum[4 * q + 0], a0.x);
        atomicAdd(&g_sum[4 * q + 1], a0.y);
        atomicAdd(&g_sum[4 * q + 2], a0.z);
        atomicAdd(&g_sum[4 * q + 3], a0.w);
        atomicAdd(&g_sum[DD + 4 * q + 0], a1.x);
        atomicAdd(&g_sum[DD + 4 * q + 1], a1.y);
        atomicAdd(&g_sum[DD + 4 * q + 2], a1.z);
        atomicAdd(&g_sum[DD + 4 * q + 3], a1.w);
    }
    __syncthreads();

    // ---- last-block election ----
    __shared__ unsigned int s_last;
    if (tid == 0) {
        __threadfence();
        unsigned int old = atomicAdd(&g_ticket, 1u);
        s_last = (old == (unsigned)(G - 1)) ? 1u : 0u;
    }
    __syncthreads();
    if (!s_last) return;

    // ---- epilogue (one block, 256 threads): GEMV + MLP ----
    __shared__ float sh0[DD], sh1[DD], xv[DD + 1], h1[HIDN], h2[HIDN];
    __shared__ float xpart[SUM_BLK];

    if (tid < DD) { sh0[tid] = g_sum[tid]; sh1[tid] = g_sum[DD + tid]; }
    __syncthreads();

    // GEMV split: col = tid&127, half = tid>>7 covers k in [64*half, 64*half+64)
    {
        const int col = tid & (DD - 1);
        const int h = tid >> 7;
        float acc = 0.0f;
#pragma unroll 8
        for (int k = h * 64; k < h * 64 + 64; k++) {
            acc += sh0[k] * W[k * DD + col];
            acc += sh1[k] * W[DD * DD + k * DD + col];
        }
        xpart[tid] = acc;
    }
    __syncthreads();
    if (tid < DD) xv[tid] = (xpart[tid] + xpart[tid + DD]) * (1.0f / (float)NN);
    if (tid == 0) xv[DD] = pt[0];
    __syncthreads();

    const int warp = tid >> 5;   // 0..7
    const int lane = tid & 31;

    // fc1: 80 x 129
    for (int row = warp; row < HIDN; row += 8) {
        float a = 0.0f;
#pragma unroll
        for (int j0 = 0; j0 < DD + 1; j0 += 32) {
            int j = j0 + lane;
            if (j < DD + 1) a += xv[j] * fc1w[row * (DD + 1) + j];
        }
        a = warp_reduce(a);
        if (lane == 0) h1[row] = lrelu(a + fc1b[row]);
    }
    __syncthreads();

    // fc2: 80 x 80
    for (int row = warp; row < HIDN; row += 8) {
        float a = 0.0f;
#pragma unroll
        for (int j0 = 0; j0 < HIDN; j0 += 32) {
            int j = j0 + lane;
            if (j < HIDN) a += h1[j] * fc2w[row * HIDN + j];
        }
        a = warp_reduce(a);
        if (lane == 0) h2[row] = lrelu(a + fc2b[row]);
    }
    __syncthreads();

    // fc3: 2 x 80
    if (warp < NOUT) {
        float a = 0.0f;
#pragma unroll
        for (int j0 = 0; j0 < HIDN; j0 += 32) {
            int j = j0 + lane;
            if (j < HIDN) a += h2[j] * fc3w[warp * HIDN + j];
        }
        a = warp_reduce(a);
        if (lane == 0) out[warp] = a + fc3b[warp];
    }

    // commit generation + reset ticket for next replay (only this block alive)
    if (tid == 0) {
        g_ticket = 0u;
        g_gen = gen;
    }
}

// ---------------------------------------------------------------------------
// Input order: nodes, edges, problem_type, W, att_w, att_b,
//              fc1_w, fc1_b, fc2_w, fc2_b, fc3_w, fc3_b
// att_w/att_b provably unused (segment softmax weights sum to 1 per dst;
// scatter-sum then makes the attention collapse to a masked column sum).
// ---------------------------------------------------------------------------
extern "C" void kernel_launch(void* const* d_in, const int* in_sizes, int n_in,
                              void* d_out, int out_size) {
    const float4* nodes4 = (const float4*)d_in[0];
    const int4*   edges4 = (const int4*)d_in[1];
    const float*  pt     = (const float*)d_in[2];
    const float*  W      = (const float*)d_in[3];
    const float*  fc1w   = (const float*)d_in[6];
    const float*  fc1b   = (const float*)d_in[7];
    const float*  fc2w   = (const float*)d_in[8];
    const float*  fc2b   = (const float*)d_in[9];
    const float*  fc3w   = (const float*)d_in[10];
    const float*  fc3b   = (const float*)d_in[11];
    float* out = (float*)d_out;

    const int mask_blocks = (SS * EE / 2 + 255) / 256;  // 2344
    k_mask<<<mask_blocks, 256>>>(edges4);
    k_sum_fused<<<SUM_GRID, SUM_BLK>>>(nodes4, W, pt,
                                       fc1w, fc1b, fc2w, fc2b, fc3w, fc3b, out);
}